// round 15
// baseline (speedup 1.0000x reference)
#include <cuda_runtime.h>
#include <cstdint>

// GraphMessagePassing on GB300 (sm_103a) — linearity-restructured fp32.
//
// messages = relu(nf[src]@W1n + ef@W1e + b1) @ w_m2 + b_m2
// agg      = segment_sum(messages, dst)
//          = (segment_sum(relu_part)) @ w_m2 + deg*b_m2            [w_m2 linear]
// out      = relu([nf, agg]@w_u1 + b_u1) @ w_u2 + b_u2
//   with agg@Wu1b = relu_sum@(w_m2@Wu1b) + deg*(b_m2@Wu1b) = relu_sum@Wc + deg*bc
//
// Pipeline:
//  1 zero      : g_relu, g_deg
//  2 prepack   : Wc = w_m2@w_u1[64:], bc = b_m2@w_u1[64:], pack k-pair weights
//  3 node_pre  : g_pre = nf@w_m1[:64] + b_m1                [N x 64 GEMM]
//  4 edge      : t = relu(g_pre[src] + ef@w_m1[64:]); RED g_relu[dst]+=t, g_deg[dst]+=1
//                (v2: direct LDG gather, 64 edges/block, 512 thr, ~9KB smem)
//  5 node      : out = relu(nf@Wu1a + g_relu@Wc + deg*bc + b_u1) @ w_u2 + b_u2

#define MAX_NODES 50000
typedef unsigned long long u64;

// ---------------- device scratch ----------------
__device__ __align__(16) float  g_pre[(size_t)MAX_NODES * 64];
__device__ __align__(16) float  g_relu[(size_t)MAX_NODES * 64];
__device__ __align__(16) float  g_deg[MAX_NODES];
__device__ __align__(16) float2 g_w1np[32 * 64];  // w_m1[:64] k-pair packed
__device__ __align__(16) float2 g_u1p[64 * 64];   // [w_u1[:64]; Wc] k-pair packed
__device__ __align__(16) float2 g_u2p[32 * 64];   // w_u2 k-pair packed
__device__ __align__(16) float  g_bc[64];         // b_m2 @ w_u1[64:]

// ---------------- helpers ----------------
__device__ __forceinline__ u64 ffma2(u64 a, u64 b, u64 c) {
    u64 d;
    asm("fma.rn.f32x2 %0, %1, %2, %3;" : "=l"(d) : "l"(a), "l"(b), "l"(c));
    return d;
}
__device__ __forceinline__ u64 pack2(float lo, float hi) {
    return ((u64)__float_as_uint(hi) << 32) | (u64)__float_as_uint(lo);
}
__device__ __forceinline__ float lo2(u64 v) { return __uint_as_float((unsigned)v); }
__device__ __forceinline__ float hi2(u64 v) { return __uint_as_float((unsigned)(v >> 32)); }
__device__ __forceinline__ float hsum(u64 v) { return lo2(v) + hi2(v); }

// ---------------- 1. zero ----------------
__global__ void zero_kernel(int nrelu4, int ndeg4) {
    int i = blockIdx.x * blockDim.x + threadIdx.x;
    float4 z = make_float4(0.f, 0.f, 0.f, 0.f);
    for (int j = i; j < nrelu4; j += gridDim.x * blockDim.x)
        ((float4*)g_relu)[j] = z;
    for (int j = i; j < ndeg4; j += gridDim.x * blockDim.x)
        ((float4*)g_deg)[j] = z;
}

// ---------------- 2. prepack (single block) ----------------
__global__ __launch_bounds__(256) void prepack_kernel(
    const float* __restrict__ w_m1, const float* __restrict__ w_m2,
    const float* __restrict__ b_m2, const float* __restrict__ w_u1,
    const float* __restrict__ w_u2) {
    __shared__ __align__(16) float sA[64 * 64];  // w_m2, then Wc
    __shared__ __align__(16) float sB[64 * 64];  // w_u1 bottom half
    int t = threadIdx.x;

    for (int i = t; i < 1024; i += 256) {
        ((float4*)sA)[i] = ((const float4*)w_m2)[i];
        ((float4*)sB)[i] = ((const float4*)(w_u1 + 64 * 64))[i];
    }
    __syncthreads();

    // Wc[k][c] = sum_j w_m2[k][j] * w_u1[64+j][c]  (into registers first)
    float wc[16];
#pragma unroll
    for (int i = 0; i < 16; i++) {
        int id = t + 256 * i;
        int k = id >> 6, c = id & 63;
        float acc = 0.f;
        for (int j = 0; j < 64; j++) acc += sA[k * 64 + j] * sB[j * 64 + c];
        wc[i] = acc;
    }
    // bc[c] = sum_j b_m2[j] * w_u1[64+j][c]
    float bc = 0.f;
    if (t < 64)
        for (int j = 0; j < 64; j++) bc += b_m2[j] * sB[j * 64 + t];
    __syncthreads();
#pragma unroll
    for (int i = 0; i < 16; i++) sA[t + 256 * i] = wc[i];  // sA := Wc
    if (t < 64) g_bc[t] = bc;
    __syncthreads();

    // pack g_w1np from w_m1 rows 0..63
    for (int i = t; i < 32 * 64; i += 256) {
        int k2 = i >> 6, c = i & 63;
        g_w1np[i] = make_float2(w_m1[(2 * k2) * 64 + c], w_m1[(2 * k2 + 1) * 64 + c]);
    }
    // pack g_u1p: rows 0..63 = w_u1 top, rows 64..127 = Wc
    for (int i = t; i < 64 * 64; i += 256) {
        int k2 = i >> 6, c = i & 63;
        float a, b;
        if (k2 < 32) {
            a = w_u1[(2 * k2) * 64 + c];
            b = w_u1[(2 * k2 + 1) * 64 + c];
        } else {
            a = sA[(2 * k2 - 64) * 64 + c];
            b = sA[(2 * k2 - 63) * 64 + c];
        }
        g_u1p[i] = make_float2(a, b);
    }
    // pack g_u2p from w_u2
    for (int i = t; i < 32 * 64; i += 256) {
        int k2 = i >> 6, c = i & 63;
        g_u2p[i] = make_float2(w_u2[(2 * k2) * 64 + c], w_u2[(2 * k2 + 1) * 64 + c]);
    }
}

// ---------------- 3. node_pre: g_pre = nf @ w_m1[:64] + b_m1 ----------------
__global__ __launch_bounds__(256) void node_pre_kernel(
    const float* __restrict__ nf, const float* __restrict__ b1, int N) {
    __shared__ __align__(16) float As[64 * 68];
    int tid = threadIdx.x;
    int base = blockIdx.x * 64;

    for (int idx = tid; idx < 64 * 16; idx += 256) {
        int r = idx >> 4, q = idx & 15;
        int n = base + r;
        if (n >= N) n = N - 1;
        *(float4*)&As[r * 68 + q * 4] = *(const float4*)&nf[(size_t)n * 64 + q * 4];
    }
    __syncthreads();

    int tc = tid & 15, tr = tid >> 4;
    u64 acc[4][4];
#pragma unroll
    for (int i = 0; i < 4; i++)
#pragma unroll
        for (int j = 0; j < 4; j++) acc[i][j] = 0ull;

    const float* A0 = As + (tr * 4 + 0) * 68;
    const float* A1 = As + (tr * 4 + 1) * 68;
    const float* A2 = As + (tr * 4 + 2) * 68;
    const float* A3 = As + (tr * 4 + 3) * 68;

#pragma unroll 4
    for (int k2 = 0; k2 < 32; ++k2) {
        u64 a[4];
        a[0] = *(const u64*)(A0 + k2 * 2);
        a[1] = *(const u64*)(A1 + k2 * 2);
        a[2] = *(const u64*)(A2 + k2 * 2);
        a[3] = *(const u64*)(A3 + k2 * 2);
        ulonglong2 wa = *(const ulonglong2*)(g_w1np + k2 * 64 + tc * 4);
        ulonglong2 wb = *(const ulonglong2*)(g_w1np + k2 * 64 + tc * 4 + 2);
        u64 w[4] = {wa.x, wa.y, wb.x, wb.y};
#pragma unroll
        for (int i = 0; i < 4; i++) {
            u64 ai = a[i];
#pragma unroll
            for (int j = 0; j < 4; j++) acc[i][j] = ffma2(ai, w[j], acc[i][j]);
        }
    }

    float4 bb = *(const float4*)(b1 + tc * 4);
#pragma unroll
    for (int i = 0; i < 4; i++) {
        int n = base + tr * 4 + i;
        if (n < N) {
            float4 o;
            o.x = hsum(acc[i][0]) + bb.x;
            o.y = hsum(acc[i][1]) + bb.y;
            o.z = hsum(acc[i][2]) + bb.z;
            o.w = hsum(acc[i][3]) + bb.w;
            *(float4*)&g_pre[(size_t)n * 64 + tc * 4] = o;
        }
    }
}

// ---------------- 4. edge kernel v2 ----------------
// 64 edges/block, 512 threads. thread = (eq = tid&63) edge x (ch = tid>>6) cols
// ch*8..ch*8+7. Accumulators seeded directly from g_pre[src] via LDG (L2-resident);
// no SMEM staging of the gathered rows.
__global__ __launch_bounds__(512) void edge_kernel(
    const float* __restrict__ ef, const int* __restrict__ src,
    const int* __restrict__ dst, const float* __restrict__ w_m1, int E) {
    __shared__ int s_src[64], s_dst[64];
    __shared__ __align__(16) float sW[16 * 64];    // w_m1 rows 64..79
    __shared__ __align__(16) float sEf[64 * 17];   // stride 17 (conflict-free)

    int tid = threadIdx.x;
    int e0 = blockIdx.x * 64;

    if (tid < 64) {
        int e = e0 + tid;
        int ec = (e < E) ? e : (E - 1);
        s_src[tid] = src[ec];
        s_dst[tid] = (e < E) ? dst[ec] : -1;
    }
    if (tid < 256)
        ((float4*)sW)[tid] = ((const float4*)(w_m1 + 4096))[tid];
    // stage edge features [64][16] -> stride 17
    {
        int idx = tid;                      // 512 threads cover 64*4 float4s in one pass
        if (idx < 64 * 4) {
            int r = idx >> 2, q = idx & 3;
            int e = e0 + r;
            if (e >= E) e = E - 1;
            float4 v = *(const float4*)&ef[(size_t)e * 16 + q * 4];
            float* p = &sEf[r * 17 + q * 4];
            p[0] = v.x; p[1] = v.y; p[2] = v.z; p[3] = v.w;
        }
    }
    __syncthreads();

    int eq = tid & 63, ch = tid >> 6;

    // seed accumulators from gathered g_pre row (direct LDG, L2 hit)
    const float* pp = &g_pre[(size_t)s_src[eq] * 64 + ch * 8];
    float4 p0 = *(const float4*)pp;
    float4 p1 = *(const float4*)(pp + 4);
    u64 acc[4] = {pack2(p0.x, p0.y), pack2(p0.z, p0.w),
                  pack2(p1.x, p1.y), pack2(p1.z, p1.w)};

    const float* efr = &sEf[eq * 17];
#pragma unroll
    for (int k = 0; k < 16; k++) {
        float a = efr[k];
        u64 av = pack2(a, a);
        const float* wr = &sW[k * 64 + ch * 8];   // warp-uniform -> broadcast
#pragma unroll
        for (int p = 0; p < 4; p++)
            acc[p] = ffma2(av, *(const u64*)(wr + 2 * p), acc[p]);
    }

    int d = s_dst[eq];
    if (d >= 0) {
        float x0 = fmaxf(lo2(acc[0]), 0.f), x1 = fmaxf(hi2(acc[0]), 0.f);
        float x2 = fmaxf(lo2(acc[1]), 0.f), x3 = fmaxf(hi2(acc[1]), 0.f);
        float x4 = fmaxf(lo2(acc[2]), 0.f), x5 = fmaxf(hi2(acc[2]), 0.f);
        float x6 = fmaxf(lo2(acc[3]), 0.f), x7 = fmaxf(hi2(acc[3]), 0.f);
        float* gp = &g_relu[(size_t)d * 64 + ch * 8];
        atomicAdd((float4*)gp, make_float4(x0, x1, x2, x3));
        atomicAdd((float4*)(gp + 4), make_float4(x4, x5, x6, x7));
        if (ch == 0) atomicAdd(&g_deg[d], 1.0f);
    }
}

// ---------------- 5. node kernel (update MLP with folded agg) ----------------
__global__ __launch_bounds__(256) void node_kernel(
    const float* __restrict__ nf, const float* __restrict__ b1,
    const float* __restrict__ b2, float* __restrict__ out, int N) {
    extern __shared__ float sm[];
    float* As = sm;             // [64][132]  cols 0..63 nf, 64..127 relu_sum
    float* Hs = sm + 64 * 132;  // [64][68]
    __shared__ float s_deg[64];

    int tid = threadIdx.x;
    int base = blockIdx.x * 64;

    for (int idx = tid; idx < 64 * 32; idx += 256) {
        int r = idx >> 5, q = idx & 31;
        int n = base + r;
        if (n >= N) n = N - 1;
        float4 v;
        if (q < 16) v = *(const float4*)&nf[(size_t)n * 64 + q * 4];
        else        v = *(const float4*)&g_relu[(size_t)n * 64 + (q - 16) * 4];
        *(float4*)&As[r * 132 + q * 4] = v;
    }
    if (tid < 64) {
        int n = base + tid;
        s_deg[tid] = (n < N) ? g_deg[n] : 0.f;
    }
    __syncthreads();

    int tc = tid & 15, tr = tid >> 4;
    u64 acc[4][4];
#pragma unroll
    for (int i = 0; i < 4; i++)
#pragma unroll
        for (int j = 0; j < 4; j++) acc[i][j] = 0ull;

    const float* A0 = As + (tr * 4 + 0) * 132;
    const float* A1 = As + (tr * 4 + 1) * 132;
    const float* A2 = As + (tr * 4 + 2) * 132;
    const float* A3 = As + (tr * 4 + 3) * 132;

#pragma unroll 4
    for (int k2 = 0; k2 < 64; ++k2) {
        u64 a[4];
        a[0] = *(const u64*)(A0 + k2 * 2);
        a[1] = *(const u64*)(A1 + k2 * 2);
        a[2] = *(const u64*)(A2 + k2 * 2);
        a[3] = *(const u64*)(A3 + k2 * 2);
        ulonglong2 wa = *(const ulonglong2*)(g_u1p + k2 * 64 + tc * 4);
        ulonglong2 wb = *(const ulonglong2*)(g_u1p + k2 * 64 + tc * 4 + 2);
        u64 w[4] = {wa.x, wa.y, wb.x, wb.y};
#pragma unroll
        for (int i = 0; i < 4; i++) {
            u64 ai = a[i];
#pragma unroll
            for (int j = 0; j < 4; j++) acc[i][j] = ffma2(ai, w[j], acc[i][j]);
        }
    }

    float4 bb1 = *(const float4*)(b1 + tc * 4);
    float4 bcv = *(const float4*)(g_bc + tc * 4);
#pragma unroll
    for (int i = 0; i < 4; i++) {
        float dg = s_deg[tr * 4 + i];
        float4 h;
        h.x = fmaxf(hsum(acc[i][0]) + bb1.x + dg * bcv.x, 0.f);
        h.y = fmaxf(hsum(acc[i][1]) + bb1.y + dg * bcv.y, 0.f);
        h.z = fmaxf(hsum(acc[i][2]) + bb1.z + dg * bcv.z, 0.f);
        h.w = fmaxf(hsum(acc[i][3]) + bb1.w + dg * bcv.w, 0.f);
        *(float4*)(Hs + (tr * 4 + i) * 68 + tc * 4) = h;
    }
    __syncthreads();

#pragma unroll
    for (int i = 0; i < 4; i++)
#pragma unroll
        for (int j = 0; j < 4; j++) acc[i][j] = 0ull;

    const float* H0 = Hs + (tr * 4 + 0) * 68;
    const float* H1 = Hs + (tr * 4 + 1) * 68;
    const float* H2 = Hs + (tr * 4 + 2) * 68;
    const float* H3 = Hs + (tr * 4 + 3) * 68;

#pragma unroll 4
    for (int k2 = 0; k2 < 32; ++k2) {
        u64 a[4];
        a[0] = *(const u64*)(H0 + k2 * 2);
        a[1] = *(const u64*)(H1 + k2 * 2);
        a[2] = *(const u64*)(H2 + k2 * 2);
        a[3] = *(const u64*)(H3 + k2 * 2);
        ulonglong2 wa = *(const ulonglong2*)(g_u2p + k2 * 64 + tc * 4);
        ulonglong2 wb = *(const ulonglong2*)(g_u2p + k2 * 64 + tc * 4 + 2);
        u64 w[4] = {wa.x, wa.y, wb.x, wb.y};
#pragma unroll
        for (int i = 0; i < 4; i++) {
            u64 ai = a[i];
#pragma unroll
            for (int j = 0; j < 4; j++) acc[i][j] = ffma2(ai, w[j], acc[i][j]);
        }
    }

    float4 bb2 = *(const float4*)(b2 + tc * 4);
#pragma unroll
    for (int i = 0; i < 4; i++) {
        int n = base + tr * 4 + i;
        if (n < N) {
            float4 o;
            o.x = hsum(acc[i][0]) + bb2.x;
            o.y = hsum(acc[i][1]) + bb2.y;
            o.z = hsum(acc[i][2]) + bb2.z;
            o.w = hsum(acc[i][3]) + bb2.w;
            *(float4*)&out[(size_t)n * 64 + tc * 4] = o;
        }
    }
}

// ---------------- launch ----------------
extern "C" void kernel_launch(void* const* d_in, const int* in_sizes, int n_in,
                              void* d_out, int out_size) {
    const float* nf   = (const float*)d_in[0];
    const float* ef   = (const float*)d_in[1];
    const int*   ei   = (const int*)d_in[2];
    const float* w_m1 = (const float*)d_in[3];
    const float* b_m1 = (const float*)d_in[4];
    const float* w_m2 = (const float*)d_in[5];
    const float* b_m2 = (const float*)d_in[6];
    const float* w_u1 = (const float*)d_in[7];
    const float* b_u1 = (const float*)d_in[8];
    const float* w_u2 = (const float*)d_in[9];
    const float* b_u2 = (const float*)d_in[10];
    float* out = (float*)d_out;

    int N = in_sizes[0] / 64;
    int E = in_sizes[2] / 2;
    const int* src = ei;
    const int* dst = ei + E;

    const int NODE_SMEM = (64 * 132 + 64 * 68) * 4;  // 51200
    cudaFuncSetAttribute((const void*)node_kernel,
                         cudaFuncAttributeMaxDynamicSharedMemorySize, NODE_SMEM);

    zero_kernel<<<592, 256>>>(N * 16, (N + 3) / 4);
    prepack_kernel<<<1, 256>>>(w_m1, w_m2, b_m2, w_u1, w_u2);

    int ntiles = (N + 63) / 64;
    node_pre_kernel<<<ntiles, 256>>>(nf, b_m1, N);

    int etiles = (E + 63) / 64;
    edge_kernel<<<etiles, 512>>>(ef, src, dst, w_m1, E);

    node_kernel<<<ntiles, 256, NODE_SMEM>>>(nf, b_u1, b_u2, out, N);
}

// round 16
// speedup vs baseline: 1.3004x; 1.3004x over previous
#include <cuda_runtime.h>
#include <cstdint>

// GraphMessagePassing on GB300 (sm_103a) — linearity-restructured fp32.
//
// messages = relu(nf[src]@W1n + ef@W1e + b1) @ w_m2 + b_m2
// agg      = segment_sum(messages, dst)
//          = (segment_sum(relu_part)) @ w_m2 + deg*b_m2            [w_m2 linear]
// out      = relu([nf, agg]@w_u1 + b_u1) @ w_u2 + b_u2
//   with agg@Wu1b = relu_sum@(w_m2@Wu1b) + deg*(b_m2@Wu1b) = relu_sum@Wc + deg*bc
//
// Pipeline:
//  1 zero      : g_relu, g_deg
//  2 prepack   : Wc = w_m2@w_u1[64:], bc = b_m2@w_u1[64:], pack k-pair weights
//  3 node_pre  : g_pre = nf@w_m1[:64] + b_m1                [N x 64 GEMM]
//  4 edge v3   : 64 edges/block, 512 thr, coalesced SMEM staging (stride 68),
//                thread = 1 edge x 8 cols, full occupancy, float4 RED scatter
//  5 node      : out = relu(nf@Wu1a + g_relu@Wc + deg*bc + b_u1) @ w_u2 + b_u2

#define MAX_NODES 50000
typedef unsigned long long u64;

// ---------------- device scratch ----------------
__device__ __align__(16) float  g_pre[(size_t)MAX_NODES * 64];
__device__ __align__(16) float  g_relu[(size_t)MAX_NODES * 64];
__device__ __align__(16) float  g_deg[MAX_NODES];
__device__ __align__(16) float2 g_w1np[32 * 64];  // w_m1[:64] k-pair packed
__device__ __align__(16) float2 g_u1p[64 * 64];   // [w_u1[:64]; Wc] k-pair packed
__device__ __align__(16) float2 g_u2p[32 * 64];   // w_u2 k-pair packed
__device__ __align__(16) float  g_bc[64];         // b_m2 @ w_u1[64:]

// ---------------- helpers ----------------
__device__ __forceinline__ u64 ffma2(u64 a, u64 b, u64 c) {
    u64 d;
    asm("fma.rn.f32x2 %0, %1, %2, %3;" : "=l"(d) : "l"(a), "l"(b), "l"(c));
    return d;
}
__device__ __forceinline__ u64 pack2(float lo, float hi) {
    return ((u64)__float_as_uint(hi) << 32) | (u64)__float_as_uint(lo);
}
__device__ __forceinline__ float lo2(u64 v) { return __uint_as_float((unsigned)v); }
__device__ __forceinline__ float hi2(u64 v) { return __uint_as_float((unsigned)(v >> 32)); }
__device__ __forceinline__ float hsum(u64 v) { return lo2(v) + hi2(v); }

// ---------------- 1. zero ----------------
__global__ void zero_kernel(int nrelu4, int ndeg4) {
    int i = blockIdx.x * blockDim.x + threadIdx.x;
    float4 z = make_float4(0.f, 0.f, 0.f, 0.f);
    for (int j = i; j < nrelu4; j += gridDim.x * blockDim.x)
        ((float4*)g_relu)[j] = z;
    for (int j = i; j < ndeg4; j += gridDim.x * blockDim.x)
        ((float4*)g_deg)[j] = z;
}

// ---------------- 2. prepack (single block) ----------------
__global__ __launch_bounds__(256) void prepack_kernel(
    const float* __restrict__ w_m1, const float* __restrict__ w_m2,
    const float* __restrict__ b_m2, const float* __restrict__ w_u1,
    const float* __restrict__ w_u2) {
    __shared__ __align__(16) float sA[64 * 64];  // w_m2, then Wc
    __shared__ __align__(16) float sB[64 * 64];  // w_u1 bottom half
    int t = threadIdx.x;

    for (int i = t; i < 1024; i += 256) {
        ((float4*)sA)[i] = ((const float4*)w_m2)[i];
        ((float4*)sB)[i] = ((const float4*)(w_u1 + 64 * 64))[i];
    }
    __syncthreads();

    // Wc[k][c] = sum_j w_m2[k][j] * w_u1[64+j][c]  (into registers first)
    float wc[16];
#pragma unroll
    for (int i = 0; i < 16; i++) {
        int id = t + 256 * i;
        int k = id >> 6, c = id & 63;
        float acc = 0.f;
        for (int j = 0; j < 64; j++) acc += sA[k * 64 + j] * sB[j * 64 + c];
        wc[i] = acc;
    }
    // bc[c] = sum_j b_m2[j] * w_u1[64+j][c]
    float bc = 0.f;
    if (t < 64)
        for (int j = 0; j < 64; j++) bc += b_m2[j] * sB[j * 64 + t];
    __syncthreads();
#pragma unroll
    for (int i = 0; i < 16; i++) sA[t + 256 * i] = wc[i];  // sA := Wc
    if (t < 64) g_bc[t] = bc;
    __syncthreads();

    // pack g_w1np from w_m1 rows 0..63
    for (int i = t; i < 32 * 64; i += 256) {
        int k2 = i >> 6, c = i & 63;
        g_w1np[i] = make_float2(w_m1[(2 * k2) * 64 + c], w_m1[(2 * k2 + 1) * 64 + c]);
    }
    // pack g_u1p: rows 0..63 = w_u1 top, rows 64..127 = Wc
    for (int i = t; i < 64 * 64; i += 256) {
        int k2 = i >> 6, c = i & 63;
        float a, b;
        if (k2 < 32) {
            a = w_u1[(2 * k2) * 64 + c];
            b = w_u1[(2 * k2 + 1) * 64 + c];
        } else {
            a = sA[(2 * k2 - 64) * 64 + c];
            b = sA[(2 * k2 - 63) * 64 + c];
        }
        g_u1p[i] = make_float2(a, b);
    }
    // pack g_u2p from w_u2
    for (int i = t; i < 32 * 64; i += 256) {
        int k2 = i >> 6, c = i & 63;
        g_u2p[i] = make_float2(w_u2[(2 * k2) * 64 + c], w_u2[(2 * k2 + 1) * 64 + c]);
    }
}

// ---------------- 3. node_pre: g_pre = nf @ w_m1[:64] + b_m1 ----------------
__global__ __launch_bounds__(256) void node_pre_kernel(
    const float* __restrict__ nf, const float* __restrict__ b1, int N) {
    __shared__ __align__(16) float As[64 * 68];
    int tid = threadIdx.x;
    int base = blockIdx.x * 64;

    for (int idx = tid; idx < 64 * 16; idx += 256) {
        int r = idx >> 4, q = idx & 15;
        int n = base + r;
        if (n >= N) n = N - 1;
        *(float4*)&As[r * 68 + q * 4] = *(const float4*)&nf[(size_t)n * 64 + q * 4];
    }
    __syncthreads();

    int tc = tid & 15, tr = tid >> 4;
    u64 acc[4][4];
#pragma unroll
    for (int i = 0; i < 4; i++)
#pragma unroll
        for (int j = 0; j < 4; j++) acc[i][j] = 0ull;

    const float* A0 = As + (tr * 4 + 0) * 68;
    const float* A1 = As + (tr * 4 + 1) * 68;
    const float* A2 = As + (tr * 4 + 2) * 68;
    const float* A3 = As + (tr * 4 + 3) * 68;

#pragma unroll 4
    for (int k2 = 0; k2 < 32; ++k2) {
        u64 a[4];
        a[0] = *(const u64*)(A0 + k2 * 2);
        a[1] = *(const u64*)(A1 + k2 * 2);
        a[2] = *(const u64*)(A2 + k2 * 2);
        a[3] = *(const u64*)(A3 + k2 * 2);
        ulonglong2 wa = *(const ulonglong2*)(g_w1np + k2 * 64 + tc * 4);
        ulonglong2 wb = *(const ulonglong2*)(g_w1np + k2 * 64 + tc * 4 + 2);
        u64 w[4] = {wa.x, wa.y, wb.x, wb.y};
#pragma unroll
        for (int i = 0; i < 4; i++) {
            u64 ai = a[i];
#pragma unroll
            for (int j = 0; j < 4; j++) acc[i][j] = ffma2(ai, w[j], acc[i][j]);
        }
    }

    float4 bb = *(const float4*)(b1 + tc * 4);
#pragma unroll
    for (int i = 0; i < 4; i++) {
        int n = base + tr * 4 + i;
        if (n < N) {
            float4 o;
            o.x = hsum(acc[i][0]) + bb.x;
            o.y = hsum(acc[i][1]) + bb.y;
            o.z = hsum(acc[i][2]) + bb.z;
            o.w = hsum(acc[i][3]) + bb.w;
            *(float4*)&g_pre[(size_t)n * 64 + tc * 4] = o;
        }
    }
}

// ---------------- 4. edge kernel v3 ----------------
// 64 edges/block, 512 threads. thread = (eq = tid&63) edge x (ch = tid>>6) cols
// ch*8..ch*8+7. Gathered g_pre rows staged coalesced into SMEM (stride 68 ->
// conflict-free LDS.128 seeds). ~26.6KB smem, ~32 regs -> 4 CTAs/SM.
__global__ __launch_bounds__(512) void edge_kernel(
    const float* __restrict__ ef, const int* __restrict__ src,
    const int* __restrict__ dst, const float* __restrict__ w_m1, int E) {
    __shared__ int s_src[64], s_dst[64];
    __shared__ __align__(16) float sW[16 * 64];    // w_m1 rows 64..79
    __shared__ __align__(16) float sEf[64 * 17];   // stride 17 (conflict-free)
    __shared__ __align__(16) float sPre[64 * 68];  // stride 68 (conflict-free v128)

    int tid = threadIdx.x;
    int e0 = blockIdx.x * 64;

    if (tid < 64) {
        int e = e0 + tid;
        int ec = (e < E) ? e : (E - 1);
        s_src[tid] = src[ec];
        s_dst[tid] = (e < E) ? dst[ec] : -1;
    }
    if (tid < 256)
        ((float4*)sW)[tid] = ((const float4*)(w_m1 + 4096))[tid];
    // stage edge features [64][16] -> stride 17 (one pass, 256 float4s)
    if (tid < 64 * 4) {
        int r = tid >> 2, q = tid & 3;
        int e = e0 + r;
        if (e >= E) e = E - 1;
        float4 v = *(const float4*)&ef[(size_t)e * 16 + q * 4];
        float* p = &sEf[r * 17 + q * 4];
        p[0] = v.x; p[1] = v.y; p[2] = v.z; p[3] = v.w;
    }
    __syncthreads();   // s_src ready before gather

    // stage gathered g_pre rows [64][64] -> stride 68, coalesced LDG per row
    for (int idx = tid; idx < 64 * 16; idx += 512) {
        int r = idx >> 4, q = idx & 15;
        float4 v = *(const float4*)&g_pre[(size_t)s_src[r] * 64 + q * 4];
        *(float4*)&sPre[r * 68 + q * 4] = v;
    }
    __syncthreads();

    int eq = tid & 63, ch = tid >> 6;

    // seed accumulators from staged row (LDS.128, conflict-free at stride 68)
    const float* pp = &sPre[eq * 68 + ch * 8];
    float4 p0 = *(const float4*)pp;
    float4 p1 = *(const float4*)(pp + 4);
    u64 acc[4] = {pack2(p0.x, p0.y), pack2(p0.z, p0.w),
                  pack2(p1.x, p1.y), pack2(p1.z, p1.w)};

    const float* efr = &sEf[eq * 17];
#pragma unroll
    for (int k = 0; k < 16; k++) {
        float a = efr[k];
        u64 av = pack2(a, a);
        const float* wr = &sW[k * 64 + ch * 8];   // warp-uniform -> broadcast
#pragma unroll
        for (int p = 0; p < 4; p++)
            acc[p] = ffma2(av, *(const u64*)(wr + 2 * p), acc[p]);
    }

    int d = s_dst[eq];
    if (d >= 0) {
        float x0 = fmaxf(lo2(acc[0]), 0.f), x1 = fmaxf(hi2(acc[0]), 0.f);
        float x2 = fmaxf(lo2(acc[1]), 0.f), x3 = fmaxf(hi2(acc[1]), 0.f);
        float x4 = fmaxf(lo2(acc[2]), 0.f), x5 = fmaxf(hi2(acc[2]), 0.f);
        float x6 = fmaxf(lo2(acc[3]), 0.f), x7 = fmaxf(hi2(acc[3]), 0.f);
        float* gp = &g_relu[(size_t)d * 64 + ch * 8];
        atomicAdd((float4*)gp, make_float4(x0, x1, x2, x3));
        atomicAdd((float4*)(gp + 4), make_float4(x4, x5, x6, x7));
        if (ch == 0) atomicAdd(&g_deg[d], 1.0f);
    }
}

// ---------------- 5. node kernel (update MLP with folded agg) ----------------
__global__ __launch_bounds__(256) void node_kernel(
    const float* __restrict__ nf, const float* __restrict__ b1,
    const float* __restrict__ b2, float* __restrict__ out, int N) {
    extern __shared__ float sm[];
    float* As = sm;             // [64][132]  cols 0..63 nf, 64..127 relu_sum
    float* Hs = sm + 64 * 132;  // [64][68]
    __shared__ float s_deg[64];

    int tid = threadIdx.x;
    int base = blockIdx.x * 64;

    for (int idx = tid; idx < 64 * 32; idx += 256) {
        int r = idx >> 5, q = idx & 31;
        int n = base + r;
        if (n >= N) n = N - 1;
        float4 v;
        if (q < 16) v = *(const float4*)&nf[(size_t)n * 64 + q * 4];
        else        v = *(const float4*)&g_relu[(size_t)n * 64 + (q - 16) * 4];
        *(float4*)&As[r * 132 + q * 4] = v;
    }
    if (tid < 64) {
        int n = base + tid;
        s_deg[tid] = (n < N) ? g_deg[n] : 0.f;
    }
    __syncthreads();

    int tc = tid & 15, tr = tid >> 4;
    u64 acc[4][4];
#pragma unroll
    for (int i = 0; i < 4; i++)
#pragma unroll
        for (int j = 0; j < 4; j++) acc[i][j] = 0ull;

    const float* A0 = As + (tr * 4 + 0) * 132;
    const float* A1 = As + (tr * 4 + 1) * 132;
    const float* A2 = As + (tr * 4 + 2) * 132;
    const float* A3 = As + (tr * 4 + 3) * 132;

#pragma unroll 4
    for (int k2 = 0; k2 < 64; ++k2) {
        u64 a[4];
        a[0] = *(const u64*)(A0 + k2 * 2);
        a[1] = *(const u64*)(A1 + k2 * 2);
        a[2] = *(const u64*)(A2 + k2 * 2);
        a[3] = *(const u64*)(A3 + k2 * 2);
        ulonglong2 wa = *(const ulonglong2*)(g_u1p + k2 * 64 + tc * 4);
        ulonglong2 wb = *(const ulonglong2*)(g_u1p + k2 * 64 + tc * 4 + 2);
        u64 w[4] = {wa.x, wa.y, wb.x, wb.y};
#pragma unroll
        for (int i = 0; i < 4; i++) {
            u64 ai = a[i];
#pragma unroll
            for (int j = 0; j < 4; j++) acc[i][j] = ffma2(ai, w[j], acc[i][j]);
        }
    }

    float4 bb1 = *(const float4*)(b1 + tc * 4);
    float4 bcv = *(const float4*)(g_bc + tc * 4);
#pragma unroll
    for (int i = 0; i < 4; i++) {
        float dg = s_deg[tr * 4 + i];
        float4 h;
        h.x = fmaxf(hsum(acc[i][0]) + bb1.x + dg * bcv.x, 0.f);
        h.y = fmaxf(hsum(acc[i][1]) + bb1.y + dg * bcv.y, 0.f);
        h.z = fmaxf(hsum(acc[i][2]) + bb1.z + dg * bcv.z, 0.f);
        h.w = fmaxf(hsum(acc[i][3]) + bb1.w + dg * bcv.w, 0.f);
        *(float4*)(Hs + (tr * 4 + i) * 68 + tc * 4) = h;
    }
    __syncthreads();

#pragma unroll
    for (int i = 0; i < 4; i++)
#pragma unroll
        for (int j = 0; j < 4; j++) acc[i][j] = 0ull;

    const float* H0 = Hs + (tr * 4 + 0) * 68;
    const float* H1 = Hs + (tr * 4 + 1) * 68;
    const float* H2 = Hs + (tr * 4 + 2) * 68;
    const float* H3 = Hs + (tr * 4 + 3) * 68;

#pragma unroll 4
    for (int k2 = 0; k2 < 32; ++k2) {
        u64 a[4];
        a[0] = *(const u64*)(H0 + k2 * 2);
        a[1] = *(const u64*)(H1 + k2 * 2);
        a[2] = *(const u64*)(H2 + k2 * 2);
        a[3] = *(const u64*)(H3 + k2 * 2);
        ulonglong2 wa = *(const ulonglong2*)(g_u2p + k2 * 64 + tc * 4);
        ulonglong2 wb = *(const ulonglong2*)(g_u2p + k2 * 64 + tc * 4 + 2);
        u64 w[4] = {wa.x, wa.y, wb.x, wb.y};
#pragma unroll
        for (int i = 0; i < 4; i++) {
            u64 ai = a[i];
#pragma unroll
            for (int j = 0; j < 4; j++) acc[i][j] = ffma2(ai, w[j], acc[i][j]);
        }
    }

    float4 bb2 = *(const float4*)(b2 + tc * 4);
#pragma unroll
    for (int i = 0; i < 4; i++) {
        int n = base + tr * 4 + i;
        if (n < N) {
            float4 o;
            o.x = hsum(acc[i][0]) + bb2.x;
            o.y = hsum(acc[i][1]) + bb2.y;
            o.z = hsum(acc[i][2]) + bb2.z;
            o.w = hsum(acc[i][3]) + bb2.w;
            *(float4*)&out[(size_t)n * 64 + tc * 4] = o;
        }
    }
}

// ---------------- launch ----------------
extern "C" void kernel_launch(void* const* d_in, const int* in_sizes, int n_in,
                              void* d_out, int out_size) {
    const float* nf   = (const float*)d_in[0];
    const float* ef   = (const float*)d_in[1];
    const int*   ei   = (const int*)d_in[2];
    const float* w_m1 = (const float*)d_in[3];
    const float* b_m1 = (const float*)d_in[4];
    const float* w_m2 = (const float*)d_in[5];
    const float* b_m2 = (const float*)d_in[6];
    const float* w_u1 = (const float*)d_in[7];
    const float* b_u1 = (const float*)d_in[8];
    const float* w_u2 = (const float*)d_in[9];
    const float* b_u2 = (const float*)d_in[10];
    float* out = (float*)d_out;

    int N = in_sizes[0] / 64;
    int E = in_sizes[2] / 2;
    const int* src = ei;
    const int* dst = ei + E;

    const int NODE_SMEM = (64 * 132 + 64 * 68) * 4;  // 51200
    cudaFuncSetAttribute((const void*)node_kernel,
                         cudaFuncAttributeMaxDynamicSharedMemorySize, NODE_SMEM);

    zero_kernel<<<592, 256>>>(N * 16, (N + 3) / 4);
    prepack_kernel<<<1, 256>>>(w_m1, w_m2, b_m2, w_u1, w_u2);

    int ntiles = (N + 63) / 64;
    node_pre_kernel<<<ntiles, 256>>>(nf, b_m1, N);

    int etiles = (E + 63) / 64;
    edge_kernel<<<etiles, 512>>>(ef, src, dst, w_m1, E);

    node_kernel<<<ntiles, 256, NODE_SMEM>>>(nf, b_u1, b_u2, out, N);
}